// round 17
// baseline (speedup 1.0000x reference)
#include <cuda_runtime.h>
#include <cstdint>

// VanillaRNN B=128,S=2048,E=256,H=512,V=128 fp32 — persistent kernel v13.
// EXACT v6 skeleton (best, 7834us): 8 row-groups x 16 CTAs, CTA = 16 B-rows
// x 32 H-cols, per-warp lane0 poll, per-warp 2-row cp.async staging in two
// overlapped k-halves, fused V-path, 32-slice SMEM reduce, butterfly out.
// Round-16 deltas (local only):
//  - SMEM-aggregated release: 8 warp arrivals -> 1 global red.release per
//    CTA (cuts LTS same-address RED serialization tail ~8x)
//  - dual-accumulator reduce (halves exposed serial-FADD chain)
//  - init merged into xw_kernel

#define Bb   128
#define Ss   2048
#define Vv   128
#define Ee   256
#define Hh   512
#define NBLK 128
#define NTHR 256

#define RR_STRIDE 516        // Δbank 4 per slice row -> conflict-free

// SMEM offsets (floats)
#define OFF_SH   0                       // h tile: 16 x 512 (plain layout)
#define OFF_WH   8192                    // Wh slice: 512 k x 32 c (unit-XOR)
#define OFF_WF   24576                   // Wfc slice: 8 cols x 512 k
#define OFF_RR   28672                   // partials: 32 x 516
#define OFF_CNT  (OFF_RR + 32 * RR_STRIDE)   // arrival counter (1 int)
#define SMEM_FLOATS (OFF_CNT + 4)
#define SMEM_BYTES  (SMEM_FLOATS * 4)

__device__ float g_h[2][Bb * Hh];        // double-buffered hidden state
__device__ float g_xw[Vv * Hh];          // token -> (emb@Wx + bx + bh)
__device__ int   g_bar8[8 * 32];         // per-row-group counters, 128B apart

static __device__ __forceinline__ float2 ffma2(float2 a, float2 b, float2 c) {
    union { float2 f; unsigned long long u; } A, B2, C;
    A.f = a; B2.f = b; C.f = c;
    asm("fma.rn.f32x2 %0, %1, %2, %0;" : "+l"(C.u) : "l"(A.u), "l"(B2.u));
    return C.f;
}

// one recursive-halving butterfly round over float2 array v[m] (V-path only)
#define BFLY2(v, m, s) {                                                  \
    const int  half_ = (m) >> 1;                                          \
    const bool up_ = (lane & (s)) != 0;                                   \
    _Pragma("unroll")                                                     \
    for (int i_ = 0; i_ < half_; ++i_) {                                  \
        float2 d_ = up_ ? v[i_] : v[i_ + half_];                          \
        float2 o_;                                                        \
        o_.x = __shfl_xor_sync(0xffffffffu, d_.x, (s));                   \
        o_.y = __shfl_xor_sync(0xffffffffu, d_.y, (s));                   \
        float2 k_ = up_ ? v[i_ + half_] : v[i_];                          \
        v[i_].x = k_.x + o_.x;                                            \
        v[i_].y = k_.y + o_.y;                                            \
    } }

// g_xw[v][:] = emb[v] @ Wx + bx + bh ; also zeroes h(-1) and counters
__global__ void __launch_bounds__(512) xw_kernel(
    const float* __restrict__ emb, const float* __restrict__ Wx,
    const float* __restrict__ bx,  const float* __restrict__ bh)
{
    __shared__ float se[Ee];
    const int v = blockIdx.x, j = threadIdx.x;
    g_h[1][v * 512 + j] = 0.0f;          // 128 blk x 512 thr = Bb*Hh exactly
    if (v == 0 && j < 8 * 32) g_bar8[j] = 0;
    if (j < Ee) se[j] = emb[v * Ee + j];
    __syncthreads();
    float acc = 0.f;
#pragma unroll 8
    for (int e = 0; e < Ee; ++e) acc = fmaf(se[e], Wx[e * Hh + j], acc);
    g_xw[v * Hh + j] = acc + bx[j] + bh[j];
}

__global__ void __launch_bounds__(NTHR, 1)
rnn_persistent(const int*   __restrict__ x,
               const float* __restrict__ Wh,
               const float* __restrict__ Wfc,
               const float* __restrict__ bfc,
               float* __restrict__ out)
{
    extern __shared__ float sm[];
    const int tid  = threadIdx.x;
    const int bidx = blockIdx.x;
    const int rgc  = bidx >> 4;          // row-group 0..7 (16 B-rows)
    const int R0   = rgc << 4;
    const int cg   = bidx & 15;
    const int C0   = cg << 5;            // 32 H-cols
    const int VC0  = cg << 3;            // 8 V-cols
    const int lane = tid & 31;
    const int ks   = lane;               // k-slice: k = m*128 + ks*4 + ki
    const int w    = tid >> 5;           // warp 0..7
    const int rowg = w >> 2;             // 0..1  -> rows rowg*8..+7
    const int colg = w & 3;              // 0..3  -> cols colg*8..+7
    const int hrow0 = rowg << 3;
    int* bar = &g_bar8[rgc * 32];
    const int x0u = (colg * 2)     ^ (ks & 7);
    const int x1u = (colg * 2 + 1) ^ (ks & 7);
    const int i2 = tid >> 4;             // 0..15
    const int j2 = (tid & 15) * 2;       // 0..30
    const int fr = lane >> 2;            // V out-path owner row

    uint32_t smem_u32;
    asm("{ .reg .u64 t0; cvta.to.shared.u64 t0, %1; cvt.u32.u64 %0, t0; }"
        : "=r"(smem_u32) : "l"(sm));
    const uint32_t cnt_addr = smem_u32 + OFF_CNT * 4;

    // ---- prologue: Wh slice (unit-XOR swizzle), Wfc slice, counter -----
    if (tid == 0) *(int*)(sm + OFF_CNT) = 0;
    for (int idx = tid; idx < Hh * 32; idx += NTHR) {
        const int k = idx >> 5, c = idx & 31;
        const int u2 = (c >> 2) ^ ((k >> 2) & 7);
        sm[OFF_WH + (k << 5) + u2 * 4 + (c & 3)] = Wh[k * Hh + C0 + c];
    }
    for (int idx = tid; idx < 8 * Hh; idx += NTHR) {
        const int c = idx >> 9, k = idx & 511;
        sm[OFF_WF + (c << 9) + k] = Wfc[k * Vv + VC0 + c];
    }
    const float2 bfcv = *(const float2*)(bfc + VC0 + colg * 2);
    __syncthreads();

    const float4* wh4 = (const float4*)(sm + OFF_WH);

    for (int t = 0; t <= Ss; ++t) {
        // ---- per-warp lane0 acquire poll (16 CTA arrivals per step) ----
        if (t > 0) {
            if (lane == 0) {
                const int target = t << 4;
                int v;
                do {
                    asm volatile("ld.acquire.gpu.global.b32 %0, [%1];"
                                 : "=r"(v) : "l"(bar) : "memory");
                } while (v - target < 0);
            }
            __syncwarp();
        }
        // ---- stage h(t-1): warp w stages rows 2w,2w+1; two k-halves ----
        const float* hsrc = g_h[(t + 1) & 1];
#pragma unroll
        for (int j = 0; j < 4; ++j) {            // half A: units 0..63
            const int idx = lane + (j << 5);
            const int row = 2 * w + (idx >> 6);
            const int u   = idx & 63;
            const uint32_t sa = smem_u32 +
                (uint32_t)((OFF_SH + (row << 9) + u * 4) * 4);
            asm volatile("cp.async.cg.shared.global [%0], [%1], 16;"
                :: "r"(sa), "l"(((const float4*)(hsrc + ((R0 + row) << 9))) + u));
        }
        asm volatile("cp.async.commit_group;");
#pragma unroll
        for (int j = 0; j < 4; ++j) {            // half B: units 64..127
            const int idx = lane + (j << 5);
            const int row = 2 * w + (idx >> 6);
            const int u   = 64 + (idx & 63);
            const uint32_t sa = smem_u32 +
                (uint32_t)((OFF_SH + (row << 9) + u * 4) * 4);
            asm volatile("cp.async.cg.shared.global [%0], [%1], 16;"
                :: "r"(sa), "l"(((const float4*)(hsrc + ((R0 + row) << 9))) + u));
        }
        asm volatile("cp.async.commit_group;");

        int tk = 0;
        if (t < Ss) tk = __ldg(x + (R0 + i2) * Ss + t);

        asm volatile("cp.async.wait_group 1;");  // half A ready
        __syncthreads();

        float2 accV[8];
#pragma unroll
        for (int r = 0; r < 8; ++r) accV[r] = make_float2(0.f, 0.f);
        float2 accR[32];
        float2 xa = make_float2(0.f, 0.f);

        if (t < Ss) {
            // prefetch xw[token] (consumed in reduce, latency hidden)
            xa = __ldg((const float2*)(g_xw + tk * Hh + C0 + j2));
#pragma unroll
            for (int p = 0; p < 32; ++p) accR[p] = make_float2(0.f, 0.f);
            // ---- compute m = 0,1 on k-half A ---------------------------
#pragma unroll
            for (int m = 0; m < 2; ++m) {
                const int ub = (m << 5) + ks;
                float4 h4[8];
#pragma unroll
                for (int r = 0; r < 8; ++r)
                    h4[r] = *(const float4*)(sm + OFF_SH
                              + ((hrow0 + r) << 9) + ub * 4);
                const float4 wfa = *(const float4*)(sm + OFF_WF
                              + ((colg * 2 + 0) << 9) + ub * 4);
                const float4 wfb = *(const float4*)(sm + OFF_WF
                              + ((colg * 2 + 1) << 9) + ub * 4);
#pragma unroll
                for (int ki = 0; ki < 4; ++ki) {
                    const int k = (m << 7) + (ks << 2) + ki;
                    const float4 wa = wh4[(k << 3) + x0u];
                    const float4 wb = wh4[(k << 3) + x1u];
                    const float2 wv = make_float2(((const float*)&wfa)[ki],
                                                  ((const float*)&wfb)[ki]);
#pragma unroll
                    for (int r = 0; r < 8; ++r) {
                        const float hv = ((const float*)&h4[r])[ki];
                        const float2 hh = make_float2(hv, hv);
                        accR[r*4+0] = ffma2(hh, make_float2(wa.x, wa.y), accR[r*4+0]);
                        accR[r*4+1] = ffma2(hh, make_float2(wa.z, wa.w), accR[r*4+1]);
                        accR[r*4+2] = ffma2(hh, make_float2(wb.x, wb.y), accR[r*4+2]);
                        accR[r*4+3] = ffma2(hh, make_float2(wb.z, wb.w), accR[r*4+3]);
                        accV[r]     = ffma2(hh, wv, accV[r]);
                    }
                }
            }
        }

        asm volatile("cp.async.wait_group 0;");  // half B ready
        __syncthreads();

        if (t < Ss) {
            // ---- compute m = 2,3 on k-half B ---------------------------
#pragma unroll
            for (int m = 2; m < 4; ++m) {
                const int ub = (m << 5) + ks;
                float4 h4[8];
#pragma unroll
                for (int r = 0; r < 8; ++r)
                    h4[r] = *(const float4*)(sm + OFF_SH
                              + ((hrow0 + r) << 9) + ub * 4);
                const float4 wfa = *(const float4*)(sm + OFF_WF
                              + ((colg * 2 + 0) << 9) + ub * 4);
                const float4 wfb = *(const float4*)(sm + OFF_WF
                              + ((colg * 2 + 1) << 9) + ub * 4);
#pragma unroll
                for (int ki = 0; ki < 4; ++ki) {
                    const int k = (m << 7) + (ks << 2) + ki;
                    const float4 wa = wh4[(k << 3) + x0u];
                    const float4 wb = wh4[(k << 3) + x1u];
                    const float2 wv = make_float2(((const float*)&wfa)[ki],
                                                  ((const float*)&wfb)[ki]);
#pragma unroll
                    for (int r = 0; r < 8; ++r) {
                        const float hv = ((const float*)&h4[r])[ki];
                        const float2 hh = make_float2(hv, hv);
                        accR[r*4+0] = ffma2(hh, make_float2(wa.x, wa.y), accR[r*4+0]);
                        accR[r*4+1] = ffma2(hh, make_float2(wa.z, wa.w), accR[r*4+1]);
                        accR[r*4+2] = ffma2(hh, make_float2(wb.x, wb.y), accR[r*4+2]);
                        accR[r*4+3] = ffma2(hh, make_float2(wb.z, wb.w), accR[r*4+3]);
                        accV[r]     = ffma2(hh, wv, accV[r]);
                    }
                }
            }
            // ---- write rec partials -----------------------------------
#pragma unroll
            for (int r = 0; r < 8; ++r) {
                float* dst = sm + OFF_RR + ks * RR_STRIDE
                             + ((hrow0 + r) << 5) + colg * 8;
                *(float4*)dst       = make_float4(accR[r*4+0].x, accR[r*4+0].y,
                                                  accR[r*4+1].x, accR[r*4+1].y);
                *(float4*)(dst + 4) = make_float4(accR[r*4+2].x, accR[r*4+2].y,
                                                  accR[r*4+3].x, accR[r*4+3].y);
            }
            __syncthreads();
            // ---- reduce 32 slices (dual acc), tanh, publish ------------
            float2 s0 = xa, s1 = make_float2(0.f, 0.f);
#pragma unroll
            for (int sl = 0; sl < 16; ++sl) {
                const float2 va = *(const float2*)(sm + OFF_RR
                                    + (2 * sl) * RR_STRIDE + tid * 2);
                const float2 vb = *(const float2*)(sm + OFF_RR
                                    + (2 * sl + 1) * RR_STRIDE + tid * 2);
                s0.x += va.x; s0.y += va.y;
                s1.x += vb.x; s1.y += vb.y;
            }
            float2 s = make_float2(tanhf(s0.x + s1.x), tanhf(s0.y + s1.y));
            *(float2*)(&g_h[t & 1][((R0 + i2) << 9) + C0 + j2]) = s;
            __syncwarp();
            // ---- aggregated release: 8 warp arrivals -> 1 global RED ---
            if (lane == 0) {
                uint32_t old;
                asm volatile("atom.acq_rel.cta.shared::cta.add.u32 %0, [%1], 1;"
                             : "=r"(old) : "r"(cnt_addr) : "memory");
                if (old == (uint32_t)(((t + 1) << 3) - 1))
                    asm volatile("red.release.gpu.global.add.s32 [%0], %1;"
                                 :: "l"(bar), "r"(1) : "memory");
            }
        } else {
            // t == Ss: output projection of h(Ss-1) only
#pragma unroll
            for (int m = 0; m < 4; ++m) {
                const int ub = (m << 5) + ks;
                const float4 wfa = *(const float4*)(sm + OFF_WF
                              + ((colg * 2 + 0) << 9) + ub * 4);
                const float4 wfb = *(const float4*)(sm + OFF_WF
                              + ((colg * 2 + 1) << 9) + ub * 4);
#pragma unroll
                for (int r = 0; r < 8; ++r) {
                    const float4 h4 = *(const float4*)(sm + OFF_SH
                              + ((hrow0 + r) << 9) + ub * 4);
#pragma unroll
                    for (int ki = 0; ki < 4; ++ki) {
                        const float hv = ((const float*)&h4)[ki];
                        const float2 wv = make_float2(((const float*)&wfa)[ki],
                                                      ((const float*)&wfb)[ki]);
                        accV[r] = ffma2(make_float2(hv, hv), wv, accV[r]);
                    }
                }
            }
        }

        // ---- out(t-1): in-warp V reduce, off inter-CTA critical path ---
        if (t > 0) {
            BFLY2(accV, 8, 16);
            BFLY2(accV, 4,  8);
            BFLY2(accV, 2,  4);
            accV[0].x += __shfl_xor_sync(0xffffffffu, accV[0].x, 2);
            accV[0].y += __shfl_xor_sync(0xffffffffu, accV[0].y, 2);
            accV[0].x += __shfl_xor_sync(0xffffffffu, accV[0].x, 1);
            accV[0].y += __shfl_xor_sync(0xffffffffu, accV[0].y, 1);
            if ((lane & 3) == 0) {
                float2 o = make_float2(accV[0].x + bfcv.x, accV[0].y + bfcv.y);
                *(float2*)(out + (long)(R0 + hrow0 + fr) * (Ss * Vv)
                           + (long)(t - 1) * Vv + VC0 + colg * 2) = o;
            }
        }
    }
}

extern "C" void kernel_launch(void* const* d_in, const int* in_sizes, int n_in,
                              void* d_out, int out_size) {
    const int*   x   = (const int*)  d_in[0];
    const float* emb = (const float*)d_in[1];
    const float* Wx  = (const float*)d_in[2];
    const float* bx  = (const float*)d_in[3];
    const float* Wh  = (const float*)d_in[4];
    const float* bh  = (const float*)d_in[5];
    const float* Wfc = (const float*)d_in[6];
    const float* bfc = (const float*)d_in[7];
    float* out = (float*)d_out;

    cudaFuncSetAttribute(rnn_persistent,
                         cudaFuncAttributeMaxDynamicSharedMemorySize, SMEM_BYTES);

    xw_kernel<<<Vv, 512>>>(emb, Wx, bx, bh);   // zeroes h(-1) + counters too
    rnn_persistent<<<NBLK, NTHR, SMEM_BYTES>>>(x, Wh, Wfc, bfc, out);
}